// round 13
// baseline (speedup 1.0000x reference)
#include <cuda_runtime.h>
#include <cstdint>
#include <math.h>

#define E 128
#define C 64
#define TILE_M 64
#define THREADS 256
#define EPSV 1e-5f
#define MAXB 512
#define SA_STRIDE 132   // floats; conflict-free fragment map, 16B aligned
#define SB_STRIDE 132

__device__ float g_part[MAXB][C + 8];
__device__ int   g_count = 0;

__device__ __forceinline__ uint32_t cvt_tf32(float f) {
    uint32_t r;
    asm("cvt.rna.tf32.f32 %0, %1;" : "=r"(r) : "f"(f));
    return r;
}

__device__ __forceinline__ void mma_tf32(float c[4], const uint32_t a[4], const uint32_t b[2]) {
    asm volatile(
        "mma.sync.aligned.m16n8k8.row.col.f32.tf32.tf32.f32 "
        "{%0,%1,%2,%3}, {%4,%5,%6,%7}, {%8,%9}, {%0,%1,%2,%3};"
        : "+f"(c[0]), "+f"(c[1]), "+f"(c[2]), "+f"(c[3])
        : "r"(a[0]), "r"(a[1]), "r"(a[2]), "r"(a[3]), "r"(b[0]), "r"(b[1]));
}

__global__ __launch_bounds__(THREADS, 2)
void cd_kernel(const float* __restrict__ node_repr,
               const float* __restrict__ maskp,
               const float* __restrict__ cent,
               float* __restrict__ out, int N) {
    extern __shared__ float smem[];
    float* sA = smem;                        // [64][SA_STRIDE], tf32-rounded
    float* sB = sA + TILE_M * SA_STRIDE;     // [64][SB_STRIDE],  tf32-rounded
    __shared__ float s_su[TILE_M], s_ru[TILE_M], s_sv[C], s_rv[C], s_mask[TILE_M];
    __shared__ float s_red[C];
    __shared__ float s_red4[4][C];
    __shared__ int s_last;
    __shared__ float s_msum;

    const int tid  = threadIdx.x;
    const int wid  = tid >> 5;
    const int lane = tid & 31;
    const int g    = lane >> 2;   // groupID
    const int tg   = lane & 3;    // thread-in-group
    const int n0   = blockIdx.x * TILE_M;
    float* node_out = out + C;

    if (tid < C) s_red[tid] = 0.0f;
    if (tid < TILE_M) {
        int n = n0 + tid;
        s_mask[tid] = (n < N) ? maskp[n] : 0.0f;
    }

    // ---- load tiles (row-major), tf32-round, row norms via warp shuffle ----
    {
        const float4* node4 = (const float4*)node_repr;
        #pragma unroll
        for (int it = 0; it < 8; it++) {      // A: 64 rows x 32 float4
            int idx = it * THREADS + tid;
            int row = idx >> 5;               // warp-uniform
            int ci  = idx & 31;
            int n = n0 + row;
            float4 v = make_float4(0.f, 0.f, 0.f, 0.f);
            if (n < N) v = node4[(size_t)n * 32 + ci];
            float4 t;
            t.x = __uint_as_float(cvt_tf32(v.x));
            t.y = __uint_as_float(cvt_tf32(v.y));
            t.z = __uint_as_float(cvt_tf32(v.z));
            t.w = __uint_as_float(cvt_tf32(v.w));
            *(float4*)(sA + row * SA_STRIDE + 4 * ci) = t;
            float s = fmaf(t.x, t.x, fmaf(t.y, t.y, fmaf(t.z, t.z, t.w * t.w)));
            #pragma unroll
            for (int off = 16; off > 0; off >>= 1) s += __shfl_xor_sync(0xFFFFFFFFu, s, off);
            if (lane == 0) s_su[row] = s;
        }
        const float4* cent4 = (const float4*)cent;
        #pragma unroll
        for (int it = 0; it < 8; it++) {      // B: 64 rows x 32 float4
            int idx = it * THREADS + tid;
            int row = idx >> 5;
            int ci  = idx & 31;
            float4 v = cent4[idx];
            float4 t;
            t.x = __uint_as_float(cvt_tf32(v.x));
            t.y = __uint_as_float(cvt_tf32(v.y));
            t.z = __uint_as_float(cvt_tf32(v.z));
            t.w = __uint_as_float(cvt_tf32(v.w));
            *(float4*)(sB + row * SB_STRIDE + 4 * ci) = t;
            float s = fmaf(t.x, t.x, fmaf(t.y, t.y, fmaf(t.z, t.z, t.w * t.w)));
            #pragma unroll
            for (int off = 16; off > 0; off >>= 1) s += __shfl_xor_sync(0xFFFFFFFFu, s, off);
            if (lane == 0) s_sv[row] = s;
        }
    }
    __syncthreads();

    if (tid < TILE_M) {
        s_ru[tid] = __fdividef(1.0f, 1.0f - s_su[tid]);
    } else if (tid < TILE_M + C) {
        int c = tid - TILE_M;
        s_rv[c] = __fdividef(1.0f, 1.0f - s_sv[c]);
    }
    __syncthreads();

    // ---- mainloop: each warp -> 32x16 tile via m16n8k8 tf32 mma.sync ----
    const int m0 = (wid & 1) * 32;            // node rows (2 groups)
    const int nq = (wid >> 1) * 16;           // centroid cols (4 groups)

    float cfr[2][2][4];
    #pragma unroll
    for (int mf = 0; mf < 2; mf++)
        #pragma unroll
        for (int nf = 0; nf < 2; nf++)
            #pragma unroll
            for (int r = 0; r < 4; r++) cfr[mf][nf][r] = 0.f;

    #pragma unroll
    for (int ks = 0; ks < 16; ks++) {
        const int k = ks * 8;
        uint32_t a[2][4], b[2][2];
        #pragma unroll
        for (int mf = 0; mf < 2; mf++) {
            const float* ar0 = sA + (m0 + mf * 16 + g) * SA_STRIDE + k + tg;
            a[mf][0] = __float_as_uint(ar0[0]);
            a[mf][2] = __float_as_uint(ar0[4]);
            a[mf][1] = __float_as_uint(ar0[8 * SA_STRIDE]);
            a[mf][3] = __float_as_uint(ar0[8 * SA_STRIDE + 4]);
        }
        #pragma unroll
        for (int nf = 0; nf < 2; nf++) {
            const float* br = sB + (nq + nf * 8 + g) * SB_STRIDE + k + tg;
            b[nf][0] = __float_as_uint(br[0]);
            b[nf][1] = __float_as_uint(br[4]);
        }
        #pragma unroll
        for (int mf = 0; mf < 2; mf++)
            #pragma unroll
            for (int nf = 0; nf < 2; nf++)
                mma_tf32(cfr[mf][nf], a[mf], b[nf]);
    }

    // ---- epilogue: series acosh, stores, graph partial sums ----
    float sv_c[2][2], rv_c[2][2];
    #pragma unroll
    for (int nf = 0; nf < 2; nf++) {
        int cc = nq + nf * 8 + 2 * tg;
        sv_c[nf][0] = s_sv[cc];     rv_c[nf][0] = s_rv[cc];
        sv_c[nf][1] = s_sv[cc + 1]; rv_c[nf][1] = s_rv[cc + 1];
    }

    float psum[2][2];
    #pragma unroll
    for (int nf = 0; nf < 2; nf++) { psum[nf][0] = 0.f; psum[nf][1] = 0.f; }

    #pragma unroll
    for (int mf = 0; mf < 2; mf++) {
        #pragma unroll
        for (int half = 0; half < 2; half++) {
            int row = m0 + mf * 16 + g + half * 8;
            int n   = n0 + row;
            float su = s_su[row];
            float ru = s_ru[row];
            float m  = s_mask[row];
            #pragma unroll
            for (int nf = 0; nf < 2; nf++) {
                float2 o;
                #pragma unroll
                for (int p = 0; p < 2; p++) {
                    float dot = cfr[mf][nf][half * 2 + p];
                    float sq  = fmaxf(fmaf(-2.f, dot, su + sv_c[nf][p]), 0.f);
                    float z   = fmaxf(sq * ru * rv_c[nf][p], 0.5f * EPSV);
                    float r   = rsqrtf(z);
                    float sz  = z * r;                        // sqrt(z)
                    float y   = 2.f * z;
                    float poly = fmaf(y, fmaf(y, fmaf(y, -0.0055803572f, 0.01875f), -0.083333336f), 1.0f);
                    float d   = 2.f * sz * poly * m;          // acosh(1+y) = sqrt(2y)*poly
                    ((float*)&o)[p] = d;
                    psum[nf][p] += d;
                }
                if (n < N)
                    *(float2*)(node_out + (size_t)n * C + nq + nf * 8 + 2 * tg) = o;
            }
        }
    }

    // reduce psum over groupID (8 groups) -> 32-row column sums
    #pragma unroll
    for (int nf = 0; nf < 2; nf++)
        #pragma unroll
        for (int p = 0; p < 2; p++) {
            float s = psum[nf][p];
            s += __shfl_xor_sync(0xFFFFFFFFu, s, 4);
            s += __shfl_xor_sync(0xFFFFFFFFu, s, 8);
            s += __shfl_xor_sync(0xFFFFFFFFu, s, 16);
            psum[nf][p] = s;
        }
    if (g == 0) {
        #pragma unroll
        for (int nf = 0; nf < 2; nf++) {
            atomicAdd(&s_red[nq + nf * 8 + 2 * tg], psum[nf][0]);
            atomicAdd(&s_red[nq + nf * 8 + 2 * tg + 1], psum[nf][1]);
        }
    }
    __syncthreads();

    // ---- per-block partials ----
    if (tid < C) g_part[blockIdx.x][tid] = s_red[tid];
    if (tid == C) {
        float ms = 0.f;
        #pragma unroll 8
        for (int i = 0; i < TILE_M; i++) ms += s_mask[i];
        g_part[blockIdx.x][C] = ms;
    }
    __threadfence();
    __syncthreads();

    if (tid == 0) s_last = (atomicAdd(&g_count, 1) == (int)gridDim.x - 1);
    __syncthreads();

    // ---- last block reduces all partials (4-way strided, unrolled for MLP) ----
    if (s_last) {
        int nb = gridDim.x;
        int c    = tid & 63;
        int part = tid >> 6;
        float s = 0.f;
        #pragma unroll 8
        for (int b = part; b < nb; b += 4) s += g_part[b][c];
        s_red4[part][c] = s;
        if (tid == 0) {
            float ms = 0.f;
            #pragma unroll 8
            for (int b = 0; b < nb; b++) ms += g_part[b][C];
            s_msum = ms;
        }
        __syncthreads();
        if (tid < C)
            out[tid] = (s_red4[0][tid] + s_red4[1][tid] + s_red4[2][tid] + s_red4[3][tid]) / s_msum;
        if (tid == 0) g_count = 0;
    }
}

extern "C" void kernel_launch(void* const* d_in, const int* in_sizes, int n_in,
                              void* d_out, int out_size) {
    const float* node_repr = (const float*)d_in[0];
    const float* maskp     = (const float*)d_in[1];
    const float* cent      = (const float*)d_in[2];
    float* out = (float*)d_out;

    int N = in_sizes[1];
    int blocks = (N + TILE_M - 1) / TILE_M;
    if (blocks > MAXB) blocks = MAXB;

    int smem_bytes = (TILE_M * SA_STRIDE + C * SB_STRIDE) * (int)sizeof(float);
    cudaFuncSetAttribute(cd_kernel, cudaFuncAttributeMaxDynamicSharedMemorySize, smem_bytes);

    cd_kernel<<<blocks, THREADS, smem_bytes>>>(node_repr, maskp, cent, out, N);
}

// round 16
// speedup vs baseline: 1.2877x; 1.2877x over previous
#include <cuda_runtime.h>
#include <cstdint>
#include <math.h>

#define E 128
#define C 64
#define TILE_M 128
#define THREADS 256
#define EPSV 1e-5f
#define MAXB 512
#define SA_STRIDE 132   // floats; fragment bank map (4g+tg) -> conflict-free
#define SB_STRIDE 132

__device__ float g_part[MAXB][C + 8];
__device__ int   g_count = 0;

__device__ __forceinline__ uint32_t smem_u32(const void* p) {
    uint32_t a;
    asm("{ .reg .u64 t; cvta.to.shared.u64 t, %1; cvt.u32.u64 %0, t; }" : "=r"(a) : "l"(p));
    return a;
}
__device__ __forceinline__ void cp_async16(uint32_t dst, const void* src) {
    asm volatile("cp.async.cg.shared.global [%0], [%1], 16;" :: "r"(dst), "l"(src));
}
#define CP_COMMIT() asm volatile("cp.async.commit_group;" ::: "memory")
#define CP_WAIT0()  asm volatile("cp.async.wait_group 0;" ::: "memory")

__device__ __forceinline__ float trunc_tf32(float x) {   // match HW tf32 truncation
    return __uint_as_float(__float_as_uint(x) & 0xFFFFE000u);
}

__device__ __forceinline__ void mma_tf32(float c[4], const uint32_t a[4], const uint32_t b[2]) {
    asm volatile(
        "mma.sync.aligned.m16n8k8.row.col.f32.tf32.tf32.f32 "
        "{%0,%1,%2,%3}, {%4,%5,%6,%7}, {%8,%9}, {%0,%1,%2,%3};"
        : "+f"(c[0]), "+f"(c[1]), "+f"(c[2]), "+f"(c[3])
        : "r"(a[0]), "r"(a[1]), "r"(a[2]), "r"(a[3]), "r"(b[0]), "r"(b[1]));
}

__global__ __launch_bounds__(THREADS, 2)
void cd_kernel(const float* __restrict__ node_repr,
               const float* __restrict__ maskp,
               const float* __restrict__ cent,
               float* __restrict__ out, int N) {
    extern __shared__ float smem[];
    float* sA = smem;                        // [128][SA_STRIDE], raw f32
    float* sB = sA + TILE_M * SA_STRIDE;     // [64][SB_STRIDE],  raw f32
    __shared__ float s_su[TILE_M], s_ru[TILE_M], s_sv[C], s_rv[C], s_mask[TILE_M];
    __shared__ float s_red[C];
    __shared__ float s_red4[4][C];
    __shared__ int s_last;
    __shared__ float s_msum;

    const int tid  = threadIdx.x;
    const int wid  = tid >> 5;
    const int lane = tid & 31;
    const int g    = lane >> 2;   // groupID
    const int tg   = lane & 3;    // thread-in-group
    const int n0   = blockIdx.x * TILE_M;
    float* node_out = out + C;

    // ---- async tile loads: gmem -> smem, no register round-trip ----
    {
        const float4* node4 = (const float4*)node_repr;
        const float4* cent4 = (const float4*)cent;
        uint32_t sA_u = smem_u32(sA);
        uint32_t sB_u = smem_u32(sB);
        #pragma unroll
        for (int it = 0; it < 16; it++) {     // A: 128 rows x 32 chunks
            int idx = it * THREADS + tid;
            int row = idx >> 5, ci = idx & 31;
            int n = n0 + row;
            if (n < N) cp_async16(sA_u + (row * SA_STRIDE + 4 * ci) * 4, node4 + (size_t)n * 32 + ci);
            else       *(float4*)(sA + row * SA_STRIDE + 4 * ci) = make_float4(0.f, 0.f, 0.f, 0.f);
        }
        #pragma unroll
        for (int it = 0; it < 8; it++) {      // B: 64 rows x 32 chunks
            int idx = it * THREADS + tid;
            int row = idx >> 5, ci = idx & 31;
            cp_async16(sB_u + (row * SB_STRIDE + 4 * ci) * 4, cent4 + row * 32 + ci);
        }
        CP_COMMIT();
    }
    if (tid < C) s_red[tid] = 0.0f;
    if (tid < TILE_M) {
        int n = n0 + tid;
        s_mask[tid] = (n < N) ? maskp[n] : 0.0f;
    }
    CP_WAIT0();
    __syncthreads();

    // ---- norms from smem (tf32-truncated bits for MMA consistency) ----
    {
        // A: 2 threads per row (128 rows)
        int rowA = tid >> 1;
        int half = tid & 1;
        const float4* ra = (const float4*)(sA + rowA * SA_STRIDE + half * 64);
        float s = 0.f;
        #pragma unroll 4
        for (int ci = 0; ci < 16; ci++) {
            float4 v = ra[ci];
            float x = trunc_tf32(v.x), y = trunc_tf32(v.y), z = trunc_tf32(v.z), w = trunc_tf32(v.w);
            s = fmaf(x, x, fmaf(y, y, fmaf(z, z, fmaf(w, w, s))));
        }
        s += __shfl_xor_sync(0xFFFFFFFFu, s, 1);
        if (half == 0) s_su[rowA] = s;

        // B: 4 threads per row (64 rows)
        int rowB = tid >> 2;
        int q    = tid & 3;
        const float4* rb = (const float4*)(sB + rowB * SB_STRIDE + q * 32);
        float sb = 0.f;
        #pragma unroll 4
        for (int ci = 0; ci < 8; ci++) {
            float4 v = rb[ci];
            float x = trunc_tf32(v.x), y = trunc_tf32(v.y), z = trunc_tf32(v.z), w = trunc_tf32(v.w);
            sb = fmaf(x, x, fmaf(y, y, fmaf(z, z, fmaf(w, w, sb))));
        }
        sb += __shfl_xor_sync(0xFFFFFFFFu, sb, 1);
        sb += __shfl_xor_sync(0xFFFFFFFFu, sb, 2);
        if (q == 0) s_sv[rowB] = sb;
    }
    __syncthreads();

    if (tid < TILE_M) {
        s_ru[tid] = __fdividef(1.0f, 1.0f - s_su[tid]);
    } else if (tid < TILE_M + C) {
        int c = tid - TILE_M;
        s_rv[c] = __fdividef(1.0f, 1.0f - s_sv[c]);
    }
    __syncthreads();

    // ---- mainloop: each warp -> 32x32 tile via m16n8k8 tf32 mma.sync ----
    const int m0 = (wid & 3) * 32;            // node rows
    const int nq = (wid >> 2) * 32;           // centroid cols

    float cfr[2][4][4];
    #pragma unroll
    for (int mf = 0; mf < 2; mf++)
        #pragma unroll
        for (int nf = 0; nf < 4; nf++)
            #pragma unroll
            for (int r = 0; r < 4; r++) cfr[mf][nf][r] = 0.f;

    #pragma unroll
    for (int ks = 0; ks < 16; ks++) {
        const int k = ks * 8;
        uint32_t a[2][4], b[4][2];
        #pragma unroll
        for (int mf = 0; mf < 2; mf++) {
            const float* ar0 = sA + (m0 + mf * 16 + g) * SA_STRIDE + k + tg;
            a[mf][0] = __float_as_uint(ar0[0]);
            a[mf][2] = __float_as_uint(ar0[4]);
            a[mf][1] = __float_as_uint(ar0[8 * SA_STRIDE]);
            a[mf][3] = __float_as_uint(ar0[8 * SA_STRIDE + 4]);
        }
        #pragma unroll
        for (int nf = 0; nf < 4; nf++) {
            const float* br = sB + (nq + nf * 8 + g) * SB_STRIDE + k + tg;
            b[nf][0] = __float_as_uint(br[0]);
            b[nf][1] = __float_as_uint(br[4]);
        }
        #pragma unroll
        for (int mf = 0; mf < 2; mf++)
            #pragma unroll
            for (int nf = 0; nf < 4; nf++)
                mma_tf32(cfr[mf][nf], a[mf], b[nf]);
    }

    // ---- epilogue: series acosh, stores, graph partial sums ----
    float sv_c[4][2], rv_c[4][2];
    #pragma unroll
    for (int nf = 0; nf < 4; nf++) {
        int cc = nq + nf * 8 + 2 * tg;
        sv_c[nf][0] = s_sv[cc];     rv_c[nf][0] = s_rv[cc];
        sv_c[nf][1] = s_sv[cc + 1]; rv_c[nf][1] = s_rv[cc + 1];
    }

    float psum[4][2];
    #pragma unroll
    for (int nf = 0; nf < 4; nf++) { psum[nf][0] = 0.f; psum[nf][1] = 0.f; }

    #pragma unroll
    for (int mf = 0; mf < 2; mf++) {
        #pragma unroll
        for (int half = 0; half < 2; half++) {
            int row = m0 + mf * 16 + g + half * 8;
            int n   = n0 + row;
            float su = s_su[row];
            float ru = s_ru[row];
            float m  = s_mask[row];
            #pragma unroll
            for (int nf = 0; nf < 4; nf++) {
                float2 o;
                #pragma unroll
                for (int p = 0; p < 2; p++) {
                    float dot = cfr[mf][nf][half * 2 + p];
                    float sq  = fmaxf(fmaf(-2.f, dot, su + sv_c[nf][p]), 0.f);
                    float z   = fmaxf(sq * ru * rv_c[nf][p], 0.5f * EPSV);
                    float r   = rsqrtf(z);
                    float sz  = z * r;                        // sqrt(z)
                    float y   = 2.f * z;
                    float poly = fmaf(y, fmaf(y, fmaf(y, -0.0055803572f, 0.01875f), -0.083333336f), 1.0f);
                    float d   = 2.f * sz * poly * m;          // acosh(1+y) = sqrt(2y)*poly
                    ((float*)&o)[p] = d;
                    psum[nf][p] += d;
                }
                if (n < N)
                    *(float2*)(node_out + (size_t)n * C + nq + nf * 8 + 2 * tg) = o;
            }
        }
    }

    // reduce psum over groupID -> 32-row column sums
    #pragma unroll
    for (int nf = 0; nf < 4; nf++)
        #pragma unroll
        for (int p = 0; p < 2; p++) {
            float s = psum[nf][p];
            s += __shfl_xor_sync(0xFFFFFFFFu, s, 4);
            s += __shfl_xor_sync(0xFFFFFFFFu, s, 8);
            s += __shfl_xor_sync(0xFFFFFFFFu, s, 16);
            psum[nf][p] = s;
        }
    if (g == 0) {
        #pragma unroll
        for (int nf = 0; nf < 4; nf++) {
            atomicAdd(&s_red[nq + nf * 8 + 2 * tg], psum[nf][0]);
            atomicAdd(&s_red[nq + nf * 8 + 2 * tg + 1], psum[nf][1]);
        }
    }
    __syncthreads();

    // ---- per-block partials ----
    if (tid < C) g_part[blockIdx.x][tid] = s_red[tid];
    if (tid == C) {
        float ms = 0.f;
        #pragma unroll 8
        for (int i = 0; i < TILE_M; i++) ms += s_mask[i];
        g_part[blockIdx.x][C] = ms;
    }
    __threadfence();
    __syncthreads();

    if (tid == 0) s_last = (atomicAdd(&g_count, 1) == (int)gridDim.x - 1);
    __syncthreads();

    // ---- last block reduces all partials (4-way strided, unrolled for MLP) ----
    if (s_last) {
        int nb = gridDim.x;
        int c    = tid & 63;
        int part = tid >> 6;
        float s = 0.f;
        #pragma unroll 8
        for (int b = part; b < nb; b += 4) s += g_part[b][c];
        s_red4[part][c] = s;
        if (tid == 0) {
            float ms = 0.f;
            #pragma unroll 8
            for (int b = 0; b < nb; b++) ms += g_part[b][C];
            s_msum = ms;
        }
        __syncthreads();
        if (tid < C)
            out[tid] = (s_red4[0][tid] + s_red4[1][tid] + s_red4[2][tid] + s_red4[3][tid]) / s_msum;
        if (tid == 0) g_count = 0;
    }
}

extern "C" void kernel_launch(void* const* d_in, const int* in_sizes, int n_in,
                              void* d_out, int out_size) {
    const float* node_repr = (const float*)d_in[0];
    const float* maskp     = (const float*)d_in[1];
    const float* cent      = (const float*)d_in[2];
    float* out = (float*)d_out;

    int N = in_sizes[1];
    int blocks = (N + TILE_M - 1) / TILE_M;
    if (blocks > MAXB) blocks = MAXB;

    int smem_bytes = (TILE_M * SA_STRIDE + C * SB_STRIDE) * (int)sizeof(float);
    cudaFuncSetAttribute(cd_kernel, cudaFuncAttributeMaxDynamicSharedMemorySize, smem_bytes);

    cd_kernel<<<blocks, THREADS, smem_bytes>>>(node_repr, maskp, cent, out, N);
}